// round 8
// baseline (speedup 1.0000x reference)
#include <cuda_runtime.h>
#include <cuda_fp16.h>
#include <cstdint>

// out[idx_row[i]] += vals[i] * flat_field[idx_col[i]], flat_field[c]=field[(c&255)<<8|(c>>8)]
// R7: 2 CTAs/SM (48 warps) for latency hiding. fp16 field[0:56576] in smem
// (110.5KB/CTA); 13.7% of gathers fall back to L2 __ldg. Scatter = REDG.ADD.F32.

#define SMEM_ELEMS 56576
#define SMEM_BYTES (SMEM_ELEMS * 2)   // 113152 B = 110.5 KB

__global__ void zero_out_kernel(float* __restrict__ out, int n) {
    int i = blockIdx.x * blockDim.x + threadIdx.x;
    if (i < n) out[i] = 0.0f;
}

__global__ void __launch_bounds__(768, 2)
spmv_smem_kernel(const float* __restrict__ field,
                 const int*   __restrict__ idx_row,
                 const int*   __restrict__ idx_col,
                 const float* __restrict__ vals,
                 float*       __restrict__ out,
                 long long nnz)
{
    extern __shared__ __half s_field[];

    // Coalesced fill: row-major field[0:SMEM_ELEMS] -> fp16 smem
    {
        const float4* f4 = reinterpret_cast<const float4*>(field);
        __half2* s2 = reinterpret_cast<__half2*>(s_field);
        for (int i = threadIdx.x; i < SMEM_ELEMS / 4; i += blockDim.x) {
            float4 f = f4[i];
            s2[2 * i]     = __floats2half2_rn(f.x, f.y);
            s2[2 * i + 1] = __floats2half2_rn(f.z, f.w);
        }
    }
    __syncthreads();

    const int4*   col4 = reinterpret_cast<const int4*>(idx_col);
    const int4*   row4 = reinterpret_cast<const int4*>(idx_row);
    const float4* val4 = reinterpret_cast<const float4*>(vals);

    long long tid    = (long long)blockIdx.x * blockDim.x + threadIdx.x;
    long long stride = (long long)gridDim.x * blockDim.x;
    long long nvec   = nnz >> 2;

    for (long long g = tid; g < nvec; g += stride) {
        int4   c = __ldcs(col4 + g);
        int4   r = __ldcs(row4 + g);
        float4 v = __ldcs(val4 + g);

        // rm = ((c & 255) << 8) | (c >> 8) in one PRMT
        unsigned rm0 = __byte_perm((unsigned)c.x, 0u, 0x4401);
        unsigned rm1 = __byte_perm((unsigned)c.y, 0u, 0x4401);
        unsigned rm2 = __byte_perm((unsigned)c.z, 0u, 0x4401);
        unsigned rm3 = __byte_perm((unsigned)c.w, 0u, 0x4401);

        float f0 = (rm0 < SMEM_ELEMS) ? __half2float(s_field[rm0]) : __ldg(field + rm0);
        float f1 = (rm1 < SMEM_ELEMS) ? __half2float(s_field[rm1]) : __ldg(field + rm1);
        float f2 = (rm2 < SMEM_ELEMS) ? __half2float(s_field[rm2]) : __ldg(field + rm2);
        float f3 = (rm3 < SMEM_ELEMS) ? __half2float(s_field[rm3]) : __ldg(field + rm3);

        atomicAdd(out + (unsigned)r.x, v.x * f0);
        atomicAdd(out + (unsigned)r.y, v.y * f1);
        atomicAdd(out + (unsigned)r.z, v.z * f2);
        atomicAdd(out + (unsigned)r.w, v.w * f3);
    }

    // tail (nnz % 4) — defensive
    long long tail_start = nvec << 2;
    for (long long i = tail_start + tid; i < nnz; i += stride) {
        unsigned rm = __byte_perm((unsigned)__ldcs(idx_col + i), 0u, 0x4401);
        float f = (rm < SMEM_ELEMS) ? __half2float(s_field[rm]) : __ldg(field + rm);
        atomicAdd(out + (unsigned)__ldcs(idx_row + i), __ldcs(vals + i) * f);
    }
}

extern "C" void kernel_launch(void* const* d_in, const int* in_sizes, int n_in,
                              void* d_out, int out_size)
{
    const float* field   = (const float*)d_in[0];
    const int*   idx_row = (const int*)d_in[1];
    const int*   idx_col = (const int*)d_in[2];
    const float* vals    = (const float*)d_in[3];
    float* out = (float*)d_out;
    long long nnz = (long long)in_sizes[1];

    {
        int threads = 256;
        int blocks = (out_size + threads - 1) / threads;
        zero_out_kernel<<<blocks, threads>>>(out, out_size);
    }
    {
        int nsm = 148;
        int dev = 0;
        if (cudaGetDevice(&dev) == cudaSuccess) {
            int q = 0;
            if (cudaDeviceGetAttribute(&q, cudaDevAttrMultiProcessorCount, dev) == cudaSuccess && q > 0)
                nsm = q;
        }
        cudaFuncSetAttribute(spmv_smem_kernel,
                             cudaFuncAttributeMaxDynamicSharedMemorySize, SMEM_BYTES);
        spmv_smem_kernel<<<2 * nsm, 768, SMEM_BYTES>>>(field, idx_row, idx_col, vals, out, nnz);
    }
}

// round 9
// speedup vs baseline: 1.0492x; 1.0492x over previous
#include <cuda_runtime.h>
#include <cuda_fp16.h>
#include <cstdint>

// out[idx_row[i]] += vals[i] * flat_field[idx_col[i]]
// flat_field[c] = field[((c&255)<<8)|(c>>8)]  (column-major flatten)
// R8: full fp16 field in smem (128KB, all gathers = LDS) + 16 nnz/thread/iter
// with 12 front-batched LDG.128 to raise per-warp MLP (latency -> throughput).

#define FIELD_ELEMS 65536
#define SMEM_BYTES  (FIELD_ELEMS * 2)   // 128 KB

__global__ void zero_out_kernel(float* __restrict__ out, int n) {
    int i = blockIdx.x * blockDim.x + threadIdx.x;
    if (i < n) out[i] = 0.0f;
}

__global__ void __launch_bounds__(1024, 1)
spmv_smem_kernel(const float* __restrict__ field,
                 const int*   __restrict__ idx_row,
                 const int*   __restrict__ idx_col,
                 const float* __restrict__ vals,
                 float*       __restrict__ out,
                 long long nnz)
{
    extern __shared__ __half s_field[];

    {   // coalesced fill, fp32 -> fp16, row-major original layout
        const float4* f4 = reinterpret_cast<const float4*>(field);
        __half2* s2 = reinterpret_cast<__half2*>(s_field);
        for (int i = threadIdx.x; i < FIELD_ELEMS / 4; i += blockDim.x) {
            float4 f = f4[i];
            s2[2 * i]     = __floats2half2_rn(f.x, f.y);
            s2[2 * i + 1] = __floats2half2_rn(f.z, f.w);
        }
    }
    __syncthreads();

    const int4*   col4 = reinterpret_cast<const int4*>(idx_col);
    const int4*   row4 = reinterpret_cast<const int4*>(idx_row);
    const float4* val4 = reinterpret_cast<const float4*>(vals);

    long long tid  = (long long)blockIdx.x * blockDim.x + threadIdx.x;
    long long T    = (long long)gridDim.x * blockDim.x;
    long long nvec = nnz >> 2;

    // Main: 4 vec4-groups (16 nnz) per thread per iteration.
    long long g = tid;
    for (; g + 3 * T < nvec; g += 4 * T) {
        int4 c[4], r[4]; float4 v[4];
        #pragma unroll
        for (int k = 0; k < 4; k++) c[k] = __ldcs(col4 + g + k * T);
        #pragma unroll
        for (int k = 0; k < 4; k++) r[k] = __ldcs(row4 + g + k * T);
        #pragma unroll
        for (int k = 0; k < 4; k++) v[k] = __ldcs(val4 + g + k * T);

        #pragma unroll
        for (int k = 0; k < 4; k++) {
            unsigned rm0 = __byte_perm((unsigned)c[k].x, 0u, 0x4401);
            unsigned rm1 = __byte_perm((unsigned)c[k].y, 0u, 0x4401);
            unsigned rm2 = __byte_perm((unsigned)c[k].z, 0u, 0x4401);
            unsigned rm3 = __byte_perm((unsigned)c[k].w, 0u, 0x4401);

            float f0 = __half2float(s_field[rm0]);
            float f1 = __half2float(s_field[rm1]);
            float f2 = __half2float(s_field[rm2]);
            float f3 = __half2float(s_field[rm3]);

            atomicAdd(out + (unsigned)r[k].x, v[k].x * f0);
            atomicAdd(out + (unsigned)r[k].y, v[k].y * f1);
            atomicAdd(out + (unsigned)r[k].z, v[k].z * f2);
            atomicAdd(out + (unsigned)r[k].w, v[k].w * f3);
        }
    }

    // Remainder groups (single-group grid-stride)
    for (; g < nvec; g += T) {
        int4   c = __ldcs(col4 + g);
        int4   r = __ldcs(row4 + g);
        float4 v = __ldcs(val4 + g);

        unsigned rm0 = __byte_perm((unsigned)c.x, 0u, 0x4401);
        unsigned rm1 = __byte_perm((unsigned)c.y, 0u, 0x4401);
        unsigned rm2 = __byte_perm((unsigned)c.z, 0u, 0x4401);
        unsigned rm3 = __byte_perm((unsigned)c.w, 0u, 0x4401);

        atomicAdd(out + (unsigned)r.x, v.x * __half2float(s_field[rm0]));
        atomicAdd(out + (unsigned)r.y, v.y * __half2float(s_field[rm1]));
        atomicAdd(out + (unsigned)r.z, v.z * __half2float(s_field[rm2]));
        atomicAdd(out + (unsigned)r.w, v.w * __half2float(s_field[rm3]));
    }

    // Tail (nnz % 4) — defensive
    long long tail_start = nvec << 2;
    for (long long i = tail_start + tid; i < nnz; i += T) {
        unsigned rm = __byte_perm((unsigned)__ldcs(idx_col + i), 0u, 0x4401);
        atomicAdd(out + (unsigned)__ldcs(idx_row + i),
                  __ldcs(vals + i) * __half2float(s_field[rm]));
    }
}

extern "C" void kernel_launch(void* const* d_in, const int* in_sizes, int n_in,
                              void* d_out, int out_size)
{
    const float* field   = (const float*)d_in[0];
    const int*   idx_row = (const int*)d_in[1];
    const int*   idx_col = (const int*)d_in[2];
    const float* vals    = (const float*)d_in[3];
    float* out = (float*)d_out;
    long long nnz = (long long)in_sizes[1];

    {
        int threads = 256;
        int blocks = (out_size + threads - 1) / threads;
        zero_out_kernel<<<blocks, threads>>>(out, out_size);
    }
    {
        int nsm = 148;
        int dev = 0;
        if (cudaGetDevice(&dev) == cudaSuccess) {
            int q = 0;
            if (cudaDeviceGetAttribute(&q, cudaDevAttrMultiProcessorCount, dev) == cudaSuccess && q > 0)
                nsm = q;
        }
        cudaFuncSetAttribute(spmv_smem_kernel,
                             cudaFuncAttributeMaxDynamicSharedMemorySize, SMEM_BYTES);
        spmv_smem_kernel<<<nsm, 1024, SMEM_BYTES>>>(field, idx_row, idx_col, vals, out, nnz);
    }
}